// round 15
// baseline (speedup 1.0000x reference)
#include <cuda_runtime.h>
#include <stdint.h>
#include <math.h>

#define Bb 4
#define Ss 128
#define Nn 512
#define Hh 64
#define Mm 2048
#define XSTR 68
#define SSTR 132
#define NTH 1024

// smem float offsets (identical to R14)
#define F_XTR  0
#define F_XTXH 8704
#define F_XTXL 17408
#define F_W    26112
#define F_VSM  43520
#define F_TAIL 52224
#define F_SC   8704
#define SMEM_FLOATS (F_TAIL + 448)

// ---------------- precomputed operands ----------------
__device__ float g_Gt[Hh*Hh];
__device__ float g_u[Hh];
__device__ float g_w[Hh];
__device__ float g_c0;
__device__ __align__(16) float g_Wsplit[4*4352];

__global__ void precompute_k(const float* __restrict__ Wq, const float* __restrict__ bq,
                             const float* __restrict__ Wk, const float* __restrict__ bk) {
    int gid = blockIdx.x * blockDim.x + threadIdx.x;
    const float scale = 0.125f;
    if (gid < Hh * Hh) {
        int c = gid >> 6, h = gid & 63;
        float s = 0.f;
        #pragma unroll 8
        for (int o = 0; o < Hh; o++) s += Wq[o*Hh + h] * Wk[o*Hh + c];
        g_Gt[gid] = s * scale;
    }
    if (gid < Hh) {
        float s = 0.f, t = 0.f;
        #pragma unroll 8
        for (int o = 0; o < Hh; o++) { s += Wq[o*Hh + gid] * bk[o]; t += Wk[o*Hh + gid] * bq[o]; }
        g_u[gid] = s * scale;
        g_w[gid] = t * scale;
    }
    if (gid == 0) {
        float s = 0.f;
        for (int o = 0; o < Hh; o++) s += bq[o] * bk[o];
        g_c0 = s * scale;
    }
}

__device__ __forceinline__ void tf32x2(float x, uint32_t& h, uint32_t& l) {
    asm("cvt.rna.tf32.f32 %0, %1;" : "=r"(h) : "f"(x));
    float r = x - __uint_as_float(h);
    asm("cvt.rna.tf32.f32 %0, %1;" : "=r"(l) : "f"(r));
}

__global__ void precompute_pack(const float* __restrict__ Wv) {
    int gid = blockIdx.x * blockDim.x + threadIdx.x;
    if (gid >= 2 * 4352) return;
    int mat = gid / 4352;
    int rem = gid % 4352;
    int r = rem / XSTR, c = rem % XSTR;
    float v = 0.f;
    if (c < 64) v = mat ? Wv[r*64 + c] : g_Gt[r*64 + c];
    uint32_t h, l;
    tf32x2(v, h, l);
    g_Wsplit[mat*8704 + rem]        = __uint_as_float(h);
    g_Wsplit[mat*8704 + 4352 + rem] = __uint_as_float(l);
}

// ---------------- mma helpers ----------------
__device__ __forceinline__ void mma8(float c[4], const uint32_t a[4], uint32_t b0, uint32_t b1) {
    asm volatile(
        "mma.sync.aligned.m16n8k8.row.col.f32.tf32.tf32.f32 "
        "{%0,%1,%2,%3}, {%4,%5,%6,%7}, {%8,%9}, {%0,%1,%2,%3};"
        : "+f"(c[0]), "+f"(c[1]), "+f"(c[2]), "+f"(c[3])
        : "r"(a[0]), "r"(a[1]), "r"(a[2]), "r"(a[3]), "r"(b0), "r"(b1));
}

__device__ __forceinline__ void gemm_fly(const float* __restrict__ A,
                                         const float* __restrict__ Bh, const float* __restrict__ Bl,
                                         int mb, int n0, int lane, float acc[4][4]) {
    const int g = lane >> 2, q = lane & 3;
    const float* ar0 = A + (mb + g) * XSTR + q;
    const float* ar1 = A + (mb + g + 8) * XSTR + q;
    #pragma unroll
    for (int k0 = 0; k0 < 64; k0 += 8) {
        uint32_t ah[4], al[4];
        tf32x2(ar0[k0],   ah[0], al[0]);
        tf32x2(ar1[k0],   ah[1], al[1]);
        tf32x2(ar0[k0+4], ah[2], al[2]);
        tf32x2(ar1[k0+4], ah[3], al[3]);
        #pragma unroll
        for (int nt = 0; nt < 4; nt++) {
            int bi = (n0 + 8*nt + g) * XSTR + k0 + q;
            uint32_t b0h = __float_as_uint(Bh[bi]), b1h = __float_as_uint(Bh[bi+4]);
            uint32_t b0l = __float_as_uint(Bl[bi]), b1l = __float_as_uint(Bl[bi+4]);
            mma8(acc[nt], ah, b0h, b1h);
            mma8(acc[nt], ah, b0l, b1l);
            mma8(acc[nt], al, b0h, b1h);
        }
    }
}

__device__ __forceinline__ void gemm_ps(const float* __restrict__ Ah, const float* __restrict__ Al,
                                        const float* __restrict__ Bh, const float* __restrict__ Bl,
                                        int mb, int n0, int lane, float acc[4][4]) {
    const int g = lane >> 2, q = lane & 3;
    const int r0 = (mb + g) * XSTR + q, r1 = (mb + g + 8) * XSTR + q;
    #pragma unroll
    for (int k0 = 0; k0 < 64; k0 += 8) {
        uint32_t ah[4], al[4];
        ah[0] = __float_as_uint(Ah[r0 + k0]);   al[0] = __float_as_uint(Al[r0 + k0]);
        ah[1] = __float_as_uint(Ah[r1 + k0]);   al[1] = __float_as_uint(Al[r1 + k0]);
        ah[2] = __float_as_uint(Ah[r0 + k0+4]); al[2] = __float_as_uint(Al[r0 + k0+4]);
        ah[3] = __float_as_uint(Ah[r1 + k0+4]); al[3] = __float_as_uint(Al[r1 + k0+4]);
        #pragma unroll
        for (int nt = 0; nt < 4; nt++) {
            int bi = (n0 + 8*nt + g) * XSTR + k0 + q;
            uint32_t b0h = __float_as_uint(Bh[bi]), b1h = __float_as_uint(Bh[bi+4]);
            uint32_t b0l = __float_as_uint(Bl[bi]), b1l = __float_as_uint(Bl[bi+4]);
            mma8(acc[nt], ah, b0h, b1h);
            mma8(acc[nt], ah, b0l, b1l);
            mma8(acc[nt], al, b0h, b1h);
        }
    }
}

__device__ __forceinline__ unsigned f2mono(float v) {
    unsigned u = __float_as_uint(v);
    return (u & 0x80000000u) ? ~u : (u | 0x80000000u);
}
__device__ __forceinline__ float mono2f(unsigned k) {
    unsigned u = (k & 0x80000000u) ? (k ^ 0x80000000u) : ~k;
    return __uint_as_float(u);
}

extern __shared__ float smf[];
__global__ void __launch_bounds__(NTH, 1)
fused_align_k(const float* __restrict__ traffic, const float* __restrict__ text,
              const float* __restrict__ Wv, const float* __restrict__ bv,
              const float* __restrict__ gamma, const float* __restrict__ beta,
              const int* __restrict__ topk_p,
              float* __restrict__ out_main, float* __restrict__ out_attn) {
    float* xt_tr = smf + F_XTR;
    float* xtxh  = smf + F_XTXH;
    float* xtxl  = smf + F_XTXL;
    float* Wr    = smf + F_W;       // Gh|Gl|Wvh|Wvl -> PH[0:8704) | PL[8704:17408)
    float* vsm   = smf + F_VSM;
    float* sc    = smf + F_SC;
    float* rb  = smf + F_TAIL;
    float* cb  = rb + 128;
    float* sg  = cb + 128;
    float* sb  = sg + 64;
    float* sbv = sb + 64;

    const int tid = threadIdx.x;
    const int lane = tid & 31;
    const int wrp = tid >> 5;
    const int m = blockIdx.x;
    const int b = m >> 9;
    const int n = m & (Nn - 1);

    const float* tr_base = traffic + ((size_t)b * Ss * Nn + n) * Hh;
    const float* tx_base = text    + ((size_t)b * Ss * Nn + n) * Hh;

    // ---- Stage 0 (identical to R14) ----
    for (int i = tid; i < 4352; i += NTH)
        ((uint4*)Wr)[i] = ((const uint4*)g_Wsplit)[i];
    #pragma unroll
    for (int it = 0; it < 2; it++) {
        int i = tid + it * NTH;
        int r = i >> 4, f = i & 15;
        float4 a  = *(const float4*)(tr_base + (size_t)r * Nn * Hh + f * 4);
        float4 bx = *(const float4*)(tx_base + (size_t)r * Nn * Hh + f * 4);
        *(float4*)(xt_tr + r * XSTR + f * 4) = a;
        uint32_t h0,l0,h1,l1,h2,l2,h3,l3;
        tf32x2(bx.x,h0,l0); tf32x2(bx.y,h1,l1); tf32x2(bx.z,h2,l2); tf32x2(bx.w,h3,l3);
        float4 hv, lv;
        hv.x=__uint_as_float(h0); hv.y=__uint_as_float(h1); hv.z=__uint_as_float(h2); hv.w=__uint_as_float(h3);
        lv.x=__uint_as_float(l0); lv.y=__uint_as_float(l1); lv.z=__uint_as_float(l2); lv.w=__uint_as_float(l3);
        *(float4*)(xtxh + r * XSTR + f * 4) = hv;
        *(float4*)(xtxl + r * XSTR + f * 4) = lv;
        float4 uu = *(const float4*)(g_u + f * 4);
        float4 ww = *(const float4*)(g_w + f * 4);
        float pr = a.x*uu.x + a.y*uu.y + a.z*uu.z + a.w*uu.w;
        float pc = bx.x*ww.x + bx.y*ww.y + bx.z*ww.z + bx.w*ww.w;
        #pragma unroll
        for (int o = 8; o > 0; o >>= 1) {
            pr += __shfl_xor_sync(0xffffffffu, pr, o);
            pc += __shfl_xor_sync(0xffffffffu, pc, o);
        }
        if (f == 0) { rb[r] = pr + g_c0; cb[r] = pc; }
    }
    if (tid < 64) { sg[tid] = gamma[tid]; sb[tid] = beta[tid]; sbv[tid] = bv[tid]; }
    __syncthreads();

    const int g = lane >> 2, q = lane & 3;

    // ---- Phase 1: P (warps 0-15) / V (warps 16-31) ----
    float accPV[4][4];
    #pragma unroll
    for (int i = 0; i < 4; i++)
        #pragma unroll
        for (int j = 0; j < 4; j++) accPV[i][j] = 0.f;
    {
        int w2 = (wrp < 16) ? wrp : (wrp - 16);
        int mb = (w2 >> 1) * 16, n0 = (w2 & 1) * 32;
        if (wrp < 16) {
            gemm_fly(xt_tr, Wr, Wr + 4352, mb, n0, lane, accPV);
        } else {
            gemm_ps(xtxh, xtxl, Wr + 8704, Wr + 13056, mb, n0, lane, accPV);
            #pragma unroll
            for (int nt = 0; nt < 4; nt++) {
                int col = n0 + 8*nt + 2*q;
                float2 o0 = { accPV[nt][0] + sbv[col], accPV[nt][1] + sbv[col+1] };
                float2 o1 = { accPV[nt][2] + sbv[col], accPV[nt][3] + sbv[col+1] };
                *(float2*)(vsm + (mb + g) * XSTR + col)     = o0;
                *(float2*)(vsm + (mb + g + 8) * XSTR + col) = o1;
            }
        }
    }
    __syncthreads();        // all G/Wv reads done
    if (wrp < 16) {         // split P -> PH [Wr], PL [Wr+8704] (overwrites dead weights)
        int mb = (wrp >> 1) * 16, n0 = (wrp & 1) * 32;
        #pragma unroll
        for (int nt = 0; nt < 4; nt++) {
            int col = n0 + 8*nt + 2*q;
            uint32_t h0, l0, h1, l1;
            tf32x2(accPV[nt][0], h0, l0); tf32x2(accPV[nt][1], h1, l1);
            *(float2*)(Wr + (mb + g) * XSTR + col)        = make_float2(__uint_as_float(h0), __uint_as_float(h1));
            *(float2*)(Wr + 8704 + (mb + g) * XSTR + col) = make_float2(__uint_as_float(l0), __uint_as_float(l1));
            tf32x2(accPV[nt][2], h0, l0); tf32x2(accPV[nt][3], h1, l1);
            *(float2*)(Wr + (mb + g + 8) * XSTR + col)        = make_float2(__uint_as_float(h0), __uint_as_float(h1));
            *(float2*)(Wr + 8704 + (mb + g + 8) * XSTR + col) = make_float2(__uint_as_float(l0), __uint_as_float(l1));
        }
    }
    __syncthreads();        // PH/PL visible

    // ---- Phase 2: S GEMM (pre-split A: no conversions) ----
    float accS[4][4];
    #pragma unroll
    for (int i = 0; i < 4; i++)
        #pragma unroll
        for (int j = 0; j < 4; j++) accS[i][j] = 0.f;
    const int smb = (wrp >> 2) * 16, sn0 = (wrp & 3) * 32;
    gemm_ps(Wr, Wr + 8704, xtxh, xtxl, smb, sn0, lane, accS);
    __syncthreads();
    #pragma unroll
    for (int nt = 0; nt < 4; nt++) {
        int col = sn0 + 8*nt + 2*q;
        float2 o0 = { accS[nt][0], accS[nt][1] };
        float2 o1 = { accS[nt][2], accS[nt][3] };
        *(float2*)(sc + (smb + g) * SSTR + col)     = o0;
        *(float2*)(sc + (smb + g + 8) * SSTR + col) = o1;
    }
    __syncthreads();

    // ---- Stage 3 (identical to R14): minimal exact top-k + post-hoc list AV ----
    int kk = 16;
    if (topk_p) { kk = topk_p[0]; if (kk < 1) kk = 1; if (kk > 32) kk = 32; }

    const int r0 = wrp * 4;
    float* attn_base = out_attn + (size_t)m * Ss * Ss;
    const unsigned FULL = 0xffffffffu;

    #pragma unroll
    for (int rp = 0; rp < 2; rp++) {
        const int sA = r0 + 2*rp;
        float o[2][4];
        unsigned kx[2][4];
        unsigned s0[2], s1[2], s2[2], s3[2];
        #pragma unroll
        for (int j = 0; j < 2; j++) {
            const int s = sA + j;
            float4 sv  = *(const float4*)(sc + s * SSTR + 4 * lane);
            float4 cbv = *(const float4*)(cb + 4 * lane);
            const float rbias = rb[s];
            o[j][0] = sv.x + rbias + cbv.x;
            o[j][1] = sv.y + rbias + cbv.y;
            o[j][2] = sv.z + rbias + cbv.z;
            o[j][3] = sv.w + rbias + cbv.w;
            #pragma unroll
            for (int t = 0; t < 4; t++) kx[j][t] = f2mono(o[j][t]);
            unsigned t0 = kx[j][0], t1 = kx[j][1], t2 = kx[j][2], t3 = kx[j][3], u;
            u = max(t0,t1); t1 = min(t0,t1); t0 = u;
            u = max(t2,t3); t3 = min(t2,t3); t2 = u;
            u = max(t0,t2); t2 = min(t0,t2); t0 = u;
            u = max(t1,t3); t3 = min(t1,t3); t1 = u;
            u = max(t1,t2); t2 = min(t1,t2); t1 = u;
            s0[j] = t0; s1[j] = t1; s2[j] = t2; s3[j] = t3;
        }

        unsigned maxk[2] = {0, 0}, thrk[2] = {0, 0};
        for (int it = 0; it < kk; ++it) {
            unsigned mw0 = __reduce_max_sync(FULL, s0[0]);
            unsigned mw1 = __reduce_max_sync(FULL, s0[1]);
            unsigned bl0 = __ballot_sync(FULL, s0[0] == mw0);
            unsigned bl1 = __ballot_sync(FULL, s0[1] == mw1);
            if (it == 0) { maxk[0] = mw0; maxk[1] = mw1; }
            thrk[0] = mw0; thrk[1] = mw1;
            if (lane == __ffs(bl0) - 1) { s0[0] = s1[0]; s1[0] = s2[0]; s2[0] = s3[0]; s3[0] = 0; }
            if (lane == __ffs(bl1) - 1) { s0[1] = s1[1]; s1[1] = s2[1]; s2[1] = s3[1]; s3[1] = 0; }
        }

        float maxv[2], z[2], inv[2], st[2][4];
        #pragma unroll
        for (int j = 0; j < 2; j++) {
            maxv[j] = mono2f(maxk[j]);
            #pragma unroll
            for (int t = 0; t < 4; t++)
                st[j][t] = (kx[j][t] >= thrk[j]) ? __expf(o[j][t] - maxv[j]) : 0.f;
            z[j] = st[j][0] + st[j][1] + st[j][2] + st[j][3];
        }
        #pragma unroll
        for (int off = 16; off > 0; off >>= 1) {
            z[0] += __shfl_xor_sync(FULL, z[0], off);
            z[1] += __shfl_xor_sync(FULL, z[1], off);
        }
        #pragma unroll
        for (int j = 0; j < 2; j++) {
            inv[j] = 1.0f / z[j];
            #pragma unroll
            for (int t = 0; t < 4; t++) st[j][t] *= inv[j];
            float4 sv4; sv4.x = st[j][0]; sv4.y = st[j][1]; sv4.z = st[j][2]; sv4.w = st[j][3];
            *(float4*)(attn_base + (size_t)(sA + j) * Ss + 4 * lane) = sv4;
        }

        int cnt[2];
        #pragma unroll
        for (int j = 0; j < 2; j++) {
            unsigned b0 = __ballot_sync(FULL, kx[j][0] >= thrk[j]);
            unsigned b1 = __ballot_sync(FULL, kx[j][1] >= thrk[j]);
            unsigned b2 = __ballot_sync(FULL, kx[j][2] >= thrk[j]);
            unsigned b3 = __ballot_sync(FULL, kx[j][3] >= thrk[j]);
            unsigned mbm = (1u << lane) - 1u;
            int off = __popc(b0 & mbm) + __popc(b1 & mbm) + __popc(b2 & mbm) + __popc(b3 & mbm);
            float2* row = (float2*)(sc + (sA + j) * SSTR);
            if (kx[j][0] >= thrk[j]) { row[off] = make_float2(st[j][0], __int_as_float(4*lane + 0)); off++; }
            if (kx[j][1] >= thrk[j]) { row[off] = make_float2(st[j][1], __int_as_float(4*lane + 1)); off++; }
            if (kx[j][2] >= thrk[j]) { row[off] = make_float2(st[j][2], __int_as_float(4*lane + 2)); off++; }
            if (kx[j][3] >= thrk[j]) { row[off] = make_float2(st[j][3], __int_as_float(4*lane + 3)); }
            cnt[j] = __popc(b0) + __popc(b1) + __popc(b2) + __popc(b3);
            if (cnt[j] > 64) cnt[j] = 64;
        }
        __syncwarp();

        float a0[2] = {0.f, 0.f}, a1[2] = {0.f, 0.f};
        const float2* rowA = (const float2*)(sc + sA * SSTR);
        const float2* rowB = (const float2*)(sc + (sA + 1) * SSTR);
        int cmax = cnt[0] > cnt[1] ? cnt[0] : cnt[1];
        for (int i2 = 0; i2 < cmax; i2++) {
            if (i2 < cnt[0]) {
                float2 pv = rowA[i2];
                const float* vr = vsm + __float_as_int(pv.y) * XSTR;
                a0[0] += pv.x * vr[lane];
                a1[0] += pv.x * vr[lane + 32];
            }
            if (i2 < cnt[1]) {
                float2 pv = rowB[i2];
                const float* vr = vsm + __float_as_int(pv.y) * XSTR;
                a0[1] += pv.x * vr[lane];
                a1[1] += pv.x * vr[lane + 32];
            }
        }

        float rr0[2], rr1[2], sm1[2];
        #pragma unroll
        for (int j = 0; j < 2; j++) {
            rr0[j] = a0[j] + xt_tr[(sA + j) * XSTR + lane];
            rr1[j] = a1[j] + xt_tr[(sA + j) * XSTR + lane + 32];
            sm1[j] = rr0[j] + rr1[j];
        }
        #pragma unroll
        for (int off = 16; off > 0; off >>= 1) {
            sm1[0] += __shfl_xor_sync(FULL, sm1[0], off);
            sm1[1] += __shfl_xor_sync(FULL, sm1[1], off);
        }
        float d0[2], d1[2], sq[2];
        #pragma unroll
        for (int j = 0; j < 2; j++) {
            float mu = sm1[j] * (1.0f / 64.0f);
            d0[j] = rr0[j] - mu; d1[j] = rr1[j] - mu;
            sq[j] = d0[j]*d0[j] + d1[j]*d1[j];
        }
        #pragma unroll
        for (int off = 16; off > 0; off >>= 1) {
            sq[0] += __shfl_xor_sync(FULL, sq[0], off);
            sq[1] += __shfl_xor_sync(FULL, sq[1], off);
        }
        #pragma unroll
        for (int j = 0; j < 2; j++) {
            float inv_sd = rsqrtf(sq[j] * (1.0f / 64.0f) + 1e-5f);
            float* ob = out_main + (((size_t)(b * Ss + sA + j)) * Nn + n) * Hh;
            ob[lane]      = d0[j] * inv_sd * sg[lane]      + sb[lane];
            ob[lane + 32] = d1[j] * inv_sd * sg[lane + 32] + sb[lane + 32];
        }
    }
}

extern "C" void kernel_launch(void* const* d_in, const int* in_sizes, int n_in,
                              void* d_out, int out_size) {
    const float* traffic = (const float*)d_in[0];
    const float* text    = (const float*)d_in[1];
    const float* Wq      = (const float*)d_in[2];
    const float* bq      = (const float*)d_in[3];
    const float* Wk      = (const float*)d_in[4];
    const float* bk      = (const float*)d_in[5];
    const float* Wv      = (const float*)d_in[6];
    const float* bv      = (const float*)d_in[7];
    const float* gamma   = (const float*)d_in[8];
    const float* beta    = (const float*)d_in[9];
    const int*   topk    = (n_in > 10) ? (const int*)d_in[10] : nullptr;

    float* out  = (float*)d_out;
    float* attn = out + (size_t)Bb * Ss * Nn * Hh;

    size_t smem = (size_t)SMEM_FLOATS * sizeof(float);
    cudaFuncSetAttribute(fused_align_k, cudaFuncAttributeMaxDynamicSharedMemorySize, (int)smem);

    precompute_k<<<16, 256>>>(Wq, bq, Wk, bk);
    precompute_pack<<<34, 256>>>(Wv);
    fused_align_k<<<Mm, NTH, smem>>>(traffic, text, Wv, bv, gamma, beta, topk, out, attn);
}

// round 16
// speedup vs baseline: 1.5251x; 1.5251x over previous
#include <cuda_runtime.h>
#include <stdint.h>
#include <math.h>

#define Bb 4
#define Ss 128
#define Nn 512
#define Hh 64
#define Mm 2048
#define XSTR 68
#define SSTR 132
#define NTH 1024

// smem float offsets (identical to R14)
#define F_XTR  0
#define F_XTXH 8704
#define F_XTXL 17408
#define F_W    26112
#define F_VSM  43520
#define F_TAIL 52224
#define F_SC   8704
#define SMEM_FLOATS (F_TAIL + 448)

// ---------------- precomputed operands ----------------
__device__ float g_u[Hh];
__device__ float g_w[Hh];
__device__ float g_c0;
__device__ __align__(16) float g_Wsplit[4*4352];   // Gh | Gl | Wvh | Wvl, [64][68] layout

__device__ __forceinline__ void tf32x2(float x, uint32_t& h, uint32_t& l) {
    asm("cvt.rna.tf32.f32 %0, %1;" : "=r"(h) : "f"(x));
    float r = x - __uint_as_float(h);
    asm("cvt.rna.tf32.f32 %0, %1;" : "=r"(l) : "f"(r));
}

// Single merged precompute: G computed inline per element, split tiles + bias vectors.
__global__ void precompute_all(const float* __restrict__ Wq, const float* __restrict__ bq,
                               const float* __restrict__ Wk, const float* __restrict__ bk,
                               const float* __restrict__ Wv) {
    int gid = blockIdx.x * blockDim.x + threadIdx.x;
    const float scale = 0.125f;
    if (gid < 2 * 4352) {
        int mat = gid / 4352;            // 0: G (computed inline), 1: Wv
        int rem = gid % 4352;
        int r = rem / XSTR, c = rem % XSTR;
        float v = 0.f;
        if (c < 64) {
            if (mat) {
                v = Wv[r*64 + c];
            } else {
                // g_Gt[r*64+c] = scale * sum_o Wq[o][c] * Wk[o][r]
                float s = 0.f;
                #pragma unroll 8
                for (int o = 0; o < Hh; o++) s += Wq[o*Hh + c] * Wk[o*Hh + r];
                v = s * scale;
            }
        }
        uint32_t h, l;
        tf32x2(v, h, l);
        g_Wsplit[mat*8704 + rem]        = __uint_as_float(h);
        g_Wsplit[mat*8704 + 4352 + rem] = __uint_as_float(l);
    }
    if (gid < Hh) {
        float s = 0.f, t = 0.f;
        #pragma unroll 8
        for (int o = 0; o < Hh; o++) { s += Wq[o*Hh + gid] * bk[o]; t += Wk[o*Hh + gid] * bq[o]; }
        g_u[gid] = s * scale;
        g_w[gid] = t * scale;
    }
    if (gid == 0) {
        float s = 0.f;
        for (int o = 0; o < Hh; o++) s += bq[o] * bk[o];
        g_c0 = s * scale;
    }
}

// ---------------- mma helpers (identical to R14) ----------------
__device__ __forceinline__ void mma8(float c[4], const uint32_t a[4], uint32_t b0, uint32_t b1) {
    asm volatile(
        "mma.sync.aligned.m16n8k8.row.col.f32.tf32.tf32.f32 "
        "{%0,%1,%2,%3}, {%4,%5,%6,%7}, {%8,%9}, {%0,%1,%2,%3};"
        : "+f"(c[0]), "+f"(c[1]), "+f"(c[2]), "+f"(c[3])
        : "r"(a[0]), "r"(a[1]), "r"(a[2]), "r"(a[3]), "r"(b0), "r"(b1));
}

__device__ __forceinline__ void gemm_fly(const float* __restrict__ A,
                                         const float* __restrict__ Bh, const float* __restrict__ Bl,
                                         int mb, int n0, int lane, float acc[4][4]) {
    const int g = lane >> 2, q = lane & 3;
    const float* ar0 = A + (mb + g) * XSTR + q;
    const float* ar1 = A + (mb + g + 8) * XSTR + q;
    #pragma unroll
    for (int k0 = 0; k0 < 64; k0 += 8) {
        uint32_t ah[4], al[4];
        tf32x2(ar0[k0],   ah[0], al[0]);
        tf32x2(ar1[k0],   ah[1], al[1]);
        tf32x2(ar0[k0+4], ah[2], al[2]);
        tf32x2(ar1[k0+4], ah[3], al[3]);
        #pragma unroll
        for (int nt = 0; nt < 4; nt++) {
            int bi = (n0 + 8*nt + g) * XSTR + k0 + q;
            uint32_t b0h = __float_as_uint(Bh[bi]), b1h = __float_as_uint(Bh[bi+4]);
            uint32_t b0l = __float_as_uint(Bl[bi]), b1l = __float_as_uint(Bl[bi+4]);
            mma8(acc[nt], ah, b0h, b1h);
            mma8(acc[nt], ah, b0l, b1l);
            mma8(acc[nt], al, b0h, b1h);
        }
    }
}

__device__ __forceinline__ void gemm_ps(const float* __restrict__ Ah, const float* __restrict__ Al,
                                        const float* __restrict__ Bh, const float* __restrict__ Bl,
                                        int mb, int n0, int lane, float acc[4][4]) {
    const int g = lane >> 2, q = lane & 3;
    const int r0 = (mb + g) * XSTR + q, r1 = (mb + g + 8) * XSTR + q;
    #pragma unroll
    for (int k0 = 0; k0 < 64; k0 += 8) {
        uint32_t ah[4], al[4];
        ah[0] = __float_as_uint(Ah[r0 + k0]);   al[0] = __float_as_uint(Al[r0 + k0]);
        ah[1] = __float_as_uint(Ah[r1 + k0]);   al[1] = __float_as_uint(Al[r1 + k0]);
        ah[2] = __float_as_uint(Ah[r0 + k0+4]); al[2] = __float_as_uint(Al[r0 + k0+4]);
        ah[3] = __float_as_uint(Ah[r1 + k0+4]); al[3] = __float_as_uint(Al[r1 + k0+4]);
        #pragma unroll
        for (int nt = 0; nt < 4; nt++) {
            int bi = (n0 + 8*nt + g) * XSTR + k0 + q;
            uint32_t b0h = __float_as_uint(Bh[bi]), b1h = __float_as_uint(Bh[bi+4]);
            uint32_t b0l = __float_as_uint(Bl[bi]), b1l = __float_as_uint(Bl[bi+4]);
            mma8(acc[nt], ah, b0h, b1h);
            mma8(acc[nt], ah, b0l, b1l);
            mma8(acc[nt], al, b0h, b1h);
        }
    }
}

__device__ __forceinline__ unsigned f2mono(float v) {
    unsigned u = __float_as_uint(v);
    return (u & 0x80000000u) ? ~u : (u | 0x80000000u);
}
__device__ __forceinline__ float mono2f(unsigned k) {
    unsigned u = (k & 0x80000000u) ? (k ^ 0x80000000u) : ~k;
    return __uint_as_float(u);
}

extern __shared__ float smf[];
__global__ void __launch_bounds__(NTH, 1)
fused_align_k(const float* __restrict__ traffic, const float* __restrict__ text,
              const float* __restrict__ Wv, const float* __restrict__ bv,
              const float* __restrict__ gamma, const float* __restrict__ beta,
              const int* __restrict__ topk_p,
              float* __restrict__ out_main, float* __restrict__ out_attn) {
    float* xt_tr = smf + F_XTR;
    float* xtxh  = smf + F_XTXH;
    float* xtxl  = smf + F_XTXL;
    float* Wr    = smf + F_W;       // Gh|Gl|Wvh|Wvl -> P fp32 overlays first 8704
    float* vsm   = smf + F_VSM;
    float* sc    = smf + F_SC;
    float* rb  = smf + F_TAIL;
    float* cb  = rb + 128;
    float* sg  = cb + 128;
    float* sb  = sg + 64;
    float* sbv = sb + 64;

    const int tid = threadIdx.x;
    const int lane = tid & 31;
    const int wrp = tid >> 5;
    const int m = blockIdx.x;
    const int b = m >> 9;
    const int n = m & (Nn - 1);

    const float* tr_base = traffic + ((size_t)b * Ss * Nn + n) * Hh;
    const float* tx_base = text    + ((size_t)b * Ss * Nn + n) * Hh;

    // ---- Stage 0 (identical to R14) ----
    for (int i = tid; i < 4352; i += NTH)
        ((uint4*)Wr)[i] = ((const uint4*)g_Wsplit)[i];
    #pragma unroll
    for (int it = 0; it < 2; it++) {
        int i = tid + it * NTH;
        int r = i >> 4, f = i & 15;
        float4 a  = *(const float4*)(tr_base + (size_t)r * Nn * Hh + f * 4);
        float4 bx = *(const float4*)(tx_base + (size_t)r * Nn * Hh + f * 4);
        *(float4*)(xt_tr + r * XSTR + f * 4) = a;
        uint32_t h0,l0,h1,l1,h2,l2,h3,l3;
        tf32x2(bx.x,h0,l0); tf32x2(bx.y,h1,l1); tf32x2(bx.z,h2,l2); tf32x2(bx.w,h3,l3);
        float4 hv, lv;
        hv.x=__uint_as_float(h0); hv.y=__uint_as_float(h1); hv.z=__uint_as_float(h2); hv.w=__uint_as_float(h3);
        lv.x=__uint_as_float(l0); lv.y=__uint_as_float(l1); lv.z=__uint_as_float(l2); lv.w=__uint_as_float(l3);
        *(float4*)(xtxh + r * XSTR + f * 4) = hv;
        *(float4*)(xtxl + r * XSTR + f * 4) = lv;
        float4 uu = *(const float4*)(g_u + f * 4);
        float4 ww = *(const float4*)(g_w + f * 4);
        float pr = a.x*uu.x + a.y*uu.y + a.z*uu.z + a.w*uu.w;
        float pc = bx.x*ww.x + bx.y*ww.y + bx.z*ww.z + bx.w*ww.w;
        #pragma unroll
        for (int o = 8; o > 0; o >>= 1) {
            pr += __shfl_xor_sync(0xffffffffu, pr, o);
            pc += __shfl_xor_sync(0xffffffffu, pc, o);
        }
        if (f == 0) { rb[r] = pr + g_c0; cb[r] = pc; }
    }
    if (tid < 64) { sg[tid] = gamma[tid]; sb[tid] = beta[tid]; sbv[tid] = bv[tid]; }
    __syncthreads();

    const int g = lane >> 2, q = lane & 3;

    // ---- Phase 1: P (warps 0-15) / V (warps 16-31) — identical to R14 ----
    float accPV[4][4];
    #pragma unroll
    for (int i = 0; i < 4; i++)
        #pragma unroll
        for (int j = 0; j < 4; j++) accPV[i][j] = 0.f;
    {
        int w2 = (wrp < 16) ? wrp : (wrp - 16);
        int mb = (w2 >> 1) * 16, n0 = (w2 & 1) * 32;
        if (wrp < 16) {
            gemm_fly(xt_tr, Wr, Wr + 4352, mb, n0, lane, accPV);
        } else {
            gemm_ps(xtxh, xtxl, Wr + 8704, Wr + 13056, mb, n0, lane, accPV);
            #pragma unroll
            for (int nt = 0; nt < 4; nt++) {
                int col = n0 + 8*nt + 2*q;
                float2 o0 = { accPV[nt][0] + sbv[col], accPV[nt][1] + sbv[col+1] };
                float2 o1 = { accPV[nt][2] + sbv[col], accPV[nt][3] + sbv[col+1] };
                *(float2*)(vsm + (mb + g) * XSTR + col)     = o0;
                *(float2*)(vsm + (mb + g + 8) * XSTR + col) = o1;
            }
        }
    }
    __syncthreads();
    if (wrp < 16) {
        int mb = (wrp >> 1) * 16, n0 = (wrp & 1) * 32;
        #pragma unroll
        for (int nt = 0; nt < 4; nt++) {
            int col = n0 + 8*nt + 2*q;
            float2 o0 = { accPV[nt][0], accPV[nt][1] };
            float2 o1 = { accPV[nt][2], accPV[nt][3] };
            *(float2*)(Wr + (mb + g) * XSTR + col)     = o0;
            *(float2*)(Wr + (mb + g + 8) * XSTR + col) = o1;
        }
    }
    __syncthreads();

    // ---- Phase 2: S GEMM (identical to R14) ----
    float accS[4][4];
    #pragma unroll
    for (int i = 0; i < 4; i++)
        #pragma unroll
        for (int j = 0; j < 4; j++) accS[i][j] = 0.f;
    const int smb = (wrp >> 2) * 16, sn0 = (wrp & 3) * 32;
    gemm_fly(Wr, xtxh, xtxl, smb, sn0, lane, accS);
    __syncthreads();
    #pragma unroll
    for (int nt = 0; nt < 4; nt++) {
        int col = sn0 + 8*nt + 2*q;
        float2 o0 = { accS[nt][0], accS[nt][1] };
        float2 o1 = { accS[nt][2], accS[nt][3] };
        *(float2*)(sc + (smb + g) * SSTR + col)     = o0;
        *(float2*)(sc + (smb + g + 8) * SSTR + col) = o1;
    }
    __syncthreads();

    // ---- Stage 3 (identical to R14): minimal exact top-k + post-hoc list AV ----
    int kk = 16;
    if (topk_p) { kk = topk_p[0]; if (kk < 1) kk = 1; if (kk > 32) kk = 32; }

    const int r0 = wrp * 4;
    float* attn_base = out_attn + (size_t)m * Ss * Ss;
    const unsigned FULL = 0xffffffffu;

    #pragma unroll
    for (int rp = 0; rp < 2; rp++) {
        const int sA = r0 + 2*rp;
        float o[2][4];
        unsigned kx[2][4];
        unsigned s0[2], s1[2], s2[2], s3[2];
        #pragma unroll
        for (int j = 0; j < 2; j++) {
            const int s = sA + j;
            float4 sv  = *(const float4*)(sc + s * SSTR + 4 * lane);
            float4 cbv = *(const float4*)(cb + 4 * lane);
            const float rbias = rb[s];
            o[j][0] = sv.x + rbias + cbv.x;
            o[j][1] = sv.y + rbias + cbv.y;
            o[j][2] = sv.z + rbias + cbv.z;
            o[j][3] = sv.w + rbias + cbv.w;
            #pragma unroll
            for (int t = 0; t < 4; t++) kx[j][t] = f2mono(o[j][t]);
            unsigned t0 = kx[j][0], t1 = kx[j][1], t2 = kx[j][2], t3 = kx[j][3], u;
            u = max(t0,t1); t1 = min(t0,t1); t0 = u;
            u = max(t2,t3); t3 = min(t2,t3); t2 = u;
            u = max(t0,t2); t2 = min(t0,t2); t0 = u;
            u = max(t1,t3); t3 = min(t1,t3); t1 = u;
            u = max(t1,t2); t2 = min(t1,t2); t1 = u;
            s0[j] = t0; s1[j] = t1; s2[j] = t2; s3[j] = t3;
        }

        unsigned maxk[2] = {0, 0}, thrk[2] = {0, 0};
        for (int it = 0; it < kk; ++it) {
            unsigned mw0 = __reduce_max_sync(FULL, s0[0]);
            unsigned mw1 = __reduce_max_sync(FULL, s0[1]);
            unsigned bl0 = __ballot_sync(FULL, s0[0] == mw0);
            unsigned bl1 = __ballot_sync(FULL, s0[1] == mw1);
            if (it == 0) { maxk[0] = mw0; maxk[1] = mw1; }
            thrk[0] = mw0; thrk[1] = mw1;
            if (lane == __ffs(bl0) - 1) { s0[0] = s1[0]; s1[0] = s2[0]; s2[0] = s3[0]; s3[0] = 0; }
            if (lane == __ffs(bl1) - 1) { s0[1] = s1[1]; s1[1] = s2[1]; s2[1] = s3[1]; s3[1] = 0; }
        }

        float maxv[2], z[2], inv[2], st[2][4];
        #pragma unroll
        for (int j = 0; j < 2; j++) {
            maxv[j] = mono2f(maxk[j]);
            #pragma unroll
            for (int t = 0; t < 4; t++)
                st[j][t] = (kx[j][t] >= thrk[j]) ? __expf(o[j][t] - maxv[j]) : 0.f;
            z[j] = st[j][0] + st[j][1] + st[j][2] + st[j][3];
        }
        #pragma unroll
        for (int off = 16; off > 0; off >>= 1) {
            z[0] += __shfl_xor_sync(FULL, z[0], off);
            z[1] += __shfl_xor_sync(FULL, z[1], off);
        }
        #pragma unroll
        for (int j = 0; j < 2; j++) {
            inv[j] = 1.0f / z[j];
            #pragma unroll
            for (int t = 0; t < 4; t++) st[j][t] *= inv[j];
            float4 sv4; sv4.x = st[j][0]; sv4.y = st[j][1]; sv4.z = st[j][2]; sv4.w = st[j][3];
            *(float4*)(attn_base + (size_t)(sA + j) * Ss + 4 * lane) = sv4;
        }

        int cnt[2];
        #pragma unroll
        for (int j = 0; j < 2; j++) {
            unsigned b0 = __ballot_sync(FULL, kx[j][0] >= thrk[j]);
            unsigned b1 = __ballot_sync(FULL, kx[j][1] >= thrk[j]);
            unsigned b2 = __ballot_sync(FULL, kx[j][2] >= thrk[j]);
            unsigned b3 = __ballot_sync(FULL, kx[j][3] >= thrk[j]);
            unsigned mbm = (1u << lane) - 1u;
            int off = __popc(b0 & mbm) + __popc(b1 & mbm) + __popc(b2 & mbm) + __popc(b3 & mbm);
            float2* row = (float2*)(sc + (sA + j) * SSTR);
            if (kx[j][0] >= thrk[j]) { row[off] = make_float2(st[j][0], __int_as_float(4*lane + 0)); off++; }
            if (kx[j][1] >= thrk[j]) { row[off] = make_float2(st[j][1], __int_as_float(4*lane + 1)); off++; }
            if (kx[j][2] >= thrk[j]) { row[off] = make_float2(st[j][2], __int_as_float(4*lane + 2)); off++; }
            if (kx[j][3] >= thrk[j]) { row[off] = make_float2(st[j][3], __int_as_float(4*lane + 3)); }
            cnt[j] = __popc(b0) + __popc(b1) + __popc(b2) + __popc(b3);
            if (cnt[j] > 64) cnt[j] = 64;
        }
        __syncwarp();

        float a0[2] = {0.f, 0.f}, a1[2] = {0.f, 0.f};
        const float2* rowA = (const float2*)(sc + sA * SSTR);
        const float2* rowB = (const float2*)(sc + (sA + 1) * SSTR);
        int cmax = cnt[0] > cnt[1] ? cnt[0] : cnt[1];
        for (int i2 = 0; i2 < cmax; i2++) {
            if (i2 < cnt[0]) {
                float2 pv = rowA[i2];
                const float* vr = vsm + __float_as_int(pv.y) * XSTR;
                a0[0] += pv.x * vr[lane];
                a1[0] += pv.x * vr[lane + 32];
            }
            if (i2 < cnt[1]) {
                float2 pv = rowB[i2];
                const float* vr = vsm + __float_as_int(pv.y) * XSTR;
                a0[1] += pv.x * vr[lane];
                a1[1] += pv.x * vr[lane + 32];
            }
        }

        float rr0[2], rr1[2], sm1[2];
        #pragma unroll
        for (int j = 0; j < 2; j++) {
            rr0[j] = a0[j] + xt_tr[(sA + j) * XSTR + lane];
            rr1[j] = a1[j] + xt_tr[(sA + j) * XSTR + lane + 32];
            sm1[j] = rr0[j] + rr1[j];
        }
        #pragma unroll
        for (int off = 16; off > 0; off >>= 1) {
            sm1[0] += __shfl_xor_sync(FULL, sm1[0], off);
            sm1[1] += __shfl_xor_sync(FULL, sm1[1], off);
        }
        float d0[2], d1[2], sq[2];
        #pragma unroll
        for (int j = 0; j < 2; j++) {
            float mu = sm1[j] * (1.0f / 64.0f);
            d0[j] = rr0[j] - mu; d1[j] = rr1[j] - mu;
            sq[j] = d0[j]*d0[j] + d1[j]*d1[j];
        }
        #pragma unroll
        for (int off = 16; off > 0; off >>= 1) {
            sq[0] += __shfl_xor_sync(FULL, sq[0], off);
            sq[1] += __shfl_xor_sync(FULL, sq[1], off);
        }
        #pragma unroll
        for (int j = 0; j < 2; j++) {
            float inv_sd = rsqrtf(sq[j] * (1.0f / 64.0f) + 1e-5f);
            float* ob = out_main + (((size_t)(b * Ss + sA + j)) * Nn + n) * Hh;
            ob[lane]      = d0[j] * inv_sd * sg[lane]      + sb[lane];
            ob[lane + 32] = d1[j] * inv_sd * sg[lane + 32] + sb[lane + 32];
        }
    }
}

extern "C" void kernel_launch(void* const* d_in, const int* in_sizes, int n_in,
                              void* d_out, int out_size) {
    const float* traffic = (const float*)d_in[0];
    const float* text    = (const float*)d_in[1];
    const float* Wq      = (const float*)d_in[2];
    const float* bq      = (const float*)d_in[3];
    const float* Wk      = (const float*)d_in[4];
    const float* bk      = (const float*)d_in[5];
    const float* Wv      = (const float*)d_in[6];
    const float* bv      = (const float*)d_in[7];
    const float* gamma   = (const float*)d_in[8];
    const float* beta    = (const float*)d_in[9];
    const int*   topk    = (n_in > 10) ? (const int*)d_in[10] : nullptr;

    float* out  = (float*)d_out;
    float* attn = out + (size_t)Bb * Ss * Nn * Hh;

    size_t smem = (size_t)SMEM_FLOATS * sizeof(float);
    cudaFuncSetAttribute(fused_align_k, cudaFuncAttributeMaxDynamicSharedMemorySize, (int)smem);

    precompute_all<<<34, 256>>>(Wq, bq, Wk, bk, Wv);
    fused_align_k<<<Mm, NTH, smem>>>(traffic, text, Wv, bv, gamma, beta, topk, out, attn);
}